// round 13
// baseline (speedup 1.0000x reference)
#include <cuda_runtime.h>

// Detection1D: B=64, N=131072, C=1. Decode + per-batch greedy NMS (TOP_K=10).
// ONE kernel, TWO symmetric CTAs per batch (128 CTAs = one wave).
//   Each CTA streams its half of clf (front-batched float4 loads, fmax
//   pre-test). Hits (score > 0.999) are decoded inline and kept in SMEM;
//   length<=3 dropped at source. Each CTA dumps its records to a small
//   global buffer and draws a 64-bit ticket (finisher count | cand count).
//   First finisher exits; the LAST finisher merges partner records (from
//   L2) with its own (still in SMEM) and runs the parallel NMS tail:
//     rank-sort (keys unique: (score<<32)|~idx = jnp.argmax order w/
//     first-index tie-break) -> pairwise IoU>0.5 bitmask -> single greedy
//     walk (provably identical to argmax+suppress).
//   Overflow/exhaustion -> exact full-N fallback (block-uniform).
// Threshold 0.999: 10th order statistic of 131072 uniforms ~0.99992 ->
// provable superset of any greedy selection; fallback covers the rest.

#define NB 64
#define NN 131072            // 2^17
#define HALF (NN / 2)
#define HALF4 (HALF / 4)     // 16384 float4 per CTA
#define NT 1024
#define UF 8
#define CAPH 192             // per-half cap (E~65, sigma~8 -> 16 sigma)
#define MCAP (2 * CAPH)      // 384
#define MW (MCAP / 32)       // 12 mask words per row
#define TOPK 10
#define THRESH 0.999f

__device__ float4 g_dump[NB * 2 * CAPH];        // (key_lo, key_hi, x1, x2)
__device__ unsigned long long g_tick[NB];       // static zero-init; winner resets

__global__ void __launch_bounds__(NT) k_all(
    const float4* __restrict__ clf4,
    const float*  __restrict__ clf,
    const float2* __restrict__ reg,
    const float2* __restrict__ prop,
    float*        __restrict__ out)
{
    const int b    = blockIdx.x >> 1;
    const int half = blockIdx.x & 1;
    const int tid  = threadIdx.x;

    __shared__ unsigned long long skey[MCAP], skey2[MCAP];
    __shared__ float sx1[MCAP], sx2[MCAP], sy1[MCAP], sy2[MCAP];
    __shared__ unsigned smask[MCAP * MW];       // 18.4 KB suppression matrix
    __shared__ float selX1[TOPK], selX2[TOPK], selSc[TOPK];
    __shared__ unsigned selIdx[TOPK];
    __shared__ int s_cnt, s_nsel, s_mode, s_last, s_oth;

    if (tid == 0) { s_cnt = 0; s_nsel = 0; s_mode = 0; }
    for (int w = tid; w < MCAP * MW; w += NT) smask[w] = 0;
    __syncthreads();

    const float2* regb  = reg  + (size_t)b * NN;
    const float2* propb = prop + (size_t)b * NN;

    // ---------- phase 1: stream my half + inline decode into SMEM -----------
    {
        const float4* c4 = clf4 + (size_t)blockIdx.x * HALF4;
        const unsigned eoff = (unsigned)half * HALF;
        for (int base = 0; base < HALF4; base += NT * UF) {     // 2 iters
            float4 v[UF];
#pragma unroll
            for (int u = 0; u < UF; u++)
                v[u] = c4[base + u * NT + tid];
#pragma unroll
            for (int u = 0; u < UF; u++) {
                float mx = fmaxf(fmaxf(v[u].x, v[u].y), fmaxf(v[u].z, v[u].w));
                if (mx > THRESH) {                  // ~1.6% of float4s
                    float ss[4] = { v[u].x, v[u].y, v[u].z, v[u].w };
                    const unsigned e0 = eoff + (unsigned)((base + u * NT + tid) * 4);
#pragma unroll
                    for (int j = 0; j < 4; j++) {
                        if (ss[j] > THRESH) {
                            unsigned idx = e0 + j;
                            float2 r = regb[idx];
                            float2 p = propb[idx];
                            float w   = p.y - p.x;
                            float ctr = p.x + 0.5f * w;
                            float pc  = ctr + (r.x * 0.1f) * w;
                            float pw  = expf(r.y * 0.2f) * w;
                            float x1 = fminf(fmaxf(pc - 0.5f * pw, 0.0f), 416.0f);
                            float x2 = fminf(fmaxf(pc + 0.5f * pw, 0.0f), 416.0f);
                            if (x2 - x1 > 3.0f) {
                                int pos = atomicAdd(&s_cnt, 1);
                                if (pos < CAPH) {
                                    skey[pos] =
                                        ((unsigned long long)__float_as_uint(ss[j]) << 32)
                                      | (unsigned long long)(0xFFFFFFFFu - idx);
                                    sx1[pos] = x1;
                                    sx2[pos] = x2;
                                }
                            }
                        }
                    }
                }
            }
        }
    }
    __syncthreads();
    const int own_cnt = s_cnt;
    const int own_m   = min(own_cnt, CAPH);

    // ---------- dump my records + draw ticket -------------------------------
    if (tid < own_m) {
        unsigned long long k = skey[tid];
        g_dump[(size_t)blockIdx.x * CAPH + tid] =
            make_float4(__uint_as_float((unsigned)(k & 0xFFFFFFFFu)),
                        __uint_as_float((unsigned)(k >> 32)),
                        sx1[tid], sx2[tid]);
        __threadfence();                            // release my record
    }
    __syncthreads();
    if (tid == 0) {
        unsigned long long tok =
            1ULL | ((unsigned long long)(unsigned)min(own_cnt, CAPH + 1) << 32);
        unsigned long long old = atomicAdd(&g_tick[b], tok);
        s_last = ((unsigned)(old & 0xFFFFFFFFu) == 1u);   // I'm the 2nd finisher
        s_oth  = (int)(old >> 32);
    }
    __syncthreads();
    if (!s_last) return;                            // block-uniform: first exits

    // ---------- winner: merge partner records -------------------------------
    const int oth_cnt = s_oth;
    const int oth_m   = min(oth_cnt, CAPH);
    const int m       = own_m + oth_m;
    if (tid == 0 && (own_cnt > CAPH || oth_cnt > CAPH)) s_mode = 1;

    {
        const float4* od = g_dump + (size_t)(blockIdx.x ^ 1) * CAPH;
        for (int i = tid; i < oth_m; i += NT) {
            float4 d = od[i];
            skey[own_m + i] =
                ((unsigned long long)__float_as_uint(d.y) << 32)
              | (unsigned long long)__float_as_uint(d.x);
            sx1[own_m + i] = d.z;
            sx2[own_m + i] = d.w;
        }
    }
    __syncthreads();

    const bool fast = (s_mode == 0);                // block-uniform

    // ---------- phase 2a: rank-sort (descending, unique keys) ---------------
    if (fast && tid < m) {
        unsigned long long myk = skey[tid];
        int rank = 0;
        for (int j = 0; j < m; j++)                 // broadcast smem reads
            rank += (skey[j] > myk);
        skey2[rank] = myk;
        sy1[rank]   = sx1[tid];
        sy2[rank]   = sx2[tid];
    }
    __syncthreads();

    // ---------- phase 2b: pairwise suppression matrix -----------------------
    if (fast) {
        const int mm = m * m;
        for (int p = tid; p < mm; p += NT) {
            int i = p / m;
            int j = p - i * m;
            if (i < j) {
                float a1 = sy1[i], a2 = sy2[i];
                float b1 = sy1[j], b2 = sy2[j];
                float inter = fmaxf(fminf(a2, b2) - fmaxf(a1, b1), 0.0f);
                float uni   = (a2 - a1) + (b2 - b1) - inter + 1e-9f;
                if (inter > 0.5f * uni)             // iou > 0.5
                    atomicOr(&smask[i * MW + (j >> 5)], 1u << (j & 31));
            }
        }
    }
    __syncthreads();

    // ---------- phase 2c: single greedy walk (thread 0) ---------------------
    if (tid == 0 && fast) {
        unsigned sup[MW];
#pragma unroll
        for (int w = 0; w < MW; w++) sup[w] = 0;
        int ns = 0;
        for (int i = 0; i < m && ns < TOPK; i++) {
            if (!((sup[i >> 5] >> (i & 31)) & 1u)) {
                unsigned long long k = skey2[i];
                selSc[ns]  = __uint_as_float((unsigned)(k >> 32));
                selIdx[ns] = 0xFFFFFFFFu - (unsigned)(k & 0xFFFFFFFFu);
                selX1[ns]  = sy1[i];
                selX2[ns]  = sy2[i];
                ns++;
#pragma unroll
                for (int w = 0; w < MW; w++)
                    sup[w] |= smask[i * MW + w];
            }
        }
        s_nsel = ns;
        if (ns < TOPK) s_mode = 1;                  // exhausted -> full-N
    }
    __syncthreads();

    // ---------- fallback: exact full-N scans (rarely/never runs) ------------
    if (s_mode == 1) {
        __shared__ unsigned long long r_key[NT / 32];
        __shared__ float r_x1[NT / 32], r_x2[NT / 32];
        const float* clfb = clf + (size_t)b * NN;
        for (int t = s_nsel; t < TOPK; t++) {
            unsigned long long best = 0ULL;
            float bx1 = 0.f, bx2 = 0.f;
            for (int i = tid; i < NN; i += NT) {
                float s = clfb[i];
                if (s <= 0.01f) continue;
                float2 r = regb[i];
                float2 p = propb[i];
                float w   = p.y - p.x;
                float ctr = p.x + 0.5f * w;
                float pc  = ctr + (r.x * 0.1f) * w;
                float pw  = expf(r.y * 0.2f) * w;
                float x1 = fminf(fmaxf(pc - 0.5f * pw, 0.0f), 416.0f);
                float x2 = fminf(fmaxf(pc + 0.5f * pw, 0.0f), 416.0f);
                float len = x2 - x1;
                if (len <= 3.0f) continue;
                bool sup = false;
                for (int j = 0; j < t; j++) {
                    if ((unsigned)i == selIdx[j]) { sup = true; break; }
                    float inter = fmaxf(fminf(x2, selX2[j]) - fmaxf(x1, selX1[j]), 0.0f);
                    float uni   = len + (selX2[j] - selX1[j]) - inter + 1e-9f;
                    if (inter / uni > 0.5f) { sup = true; break; }
                }
                if (sup) continue;
                unsigned long long k =
                    ((unsigned long long)__float_as_uint(s) << 32)
                  | (unsigned long long)(0xFFFFFFFFu - (unsigned)i);
                if (k > best) { best = k; bx1 = x1; bx2 = x2; }
            }
#pragma unroll
            for (int o = 16; o > 0; o >>= 1) {
                unsigned long long k2 = __shfl_down_sync(0xFFFFFFFFu, best, o);
                float a2 = __shfl_down_sync(0xFFFFFFFFu, bx1, o);
                float b2 = __shfl_down_sync(0xFFFFFFFFu, bx2, o);
                if (k2 > best) { best = k2; bx1 = a2; bx2 = b2; }
            }
            if ((tid & 31) == 0) {
                int w = tid >> 5;
                r_key[w] = best; r_x1[w] = bx1; r_x2[w] = bx2;
            }
            __syncthreads();
            if (tid == 0) {
                best = 0ULL;
                for (int w = 0; w < NT / 32; w++)
                    if (r_key[w] > best) { best = r_key[w]; bx1 = r_x1[w]; bx2 = r_x2[w]; }
                if (best == 0ULL) {
                    s_mode = 2;   // nothing left -> -1 rows from here on
                } else {
                    selSc[t]  = __uint_as_float((unsigned)(best >> 32));
                    selIdx[t] = 0xFFFFFFFFu - (unsigned)(best & 0xFFFFFFFFu);
                    selX1[t]  = bx1;
                    selX2[t]  = bx2;
                    s_nsel = t + 1;
                }
            }
            __syncthreads();
            if (s_mode == 2) break;
        }
    }

    __syncthreads();
    if (tid < TOPK) {
        int t = tid;
        float a = -1.0f, c = -1.0f, s = -1.0f;
        if (t < s_nsel) { a = selX1[t]; c = selX2[t]; s = selSc[t]; }
        out[b * (TOPK * 3) + t * 3 + 0] = a;
        out[b * (TOPK * 3) + t * 3 + 1] = c;
        out[b * (TOPK * 3) + t * 3 + 2] = s;
    }
    if (tid == 0) g_tick[b] = 0;                    // replay-clean
}

extern "C" void kernel_launch(void* const* d_in, const int* in_sizes, int n_in,
                              void* d_out, int out_size)
{
    const float*  clf  = (const float*)d_in[0];                 // (64,131072,1)
    const float2* reg  = (const float2*)d_in[1];                // (64,131072,2)
    const float2* prop = (const float2*)d_in[2];                // (64,131072,2)
    float* out = (float*)d_out;                                 // (64,10,3)

    k_all<<<NB * 2, NT>>>((const float4*)clf, clf, reg, prop, out);
}